// round 8
// baseline (speedup 1.0000x reference)
#include <cuda_runtime.h>
#include <cuda_bf16.h>
#include <cstdint>
#include <math.h>

// Problem constants
#define BATCH 2
#define SEQ   2048
#define EMB   2048
#define NHEAD 16
#define DHEAD 128
#define NEXP_ 64
#define RLORA 32
#define ROWS  4096          // BATCH*SEQ
#define KAUG  2144          // EMB + RLORA + NEXP_
#define KP8   2176          // padded to 64*34
#define NCH   34            // 64-wide K chunks

// ---------------- scratch (static device globals; no allocations) ----------
__device__ float g_q[(size_t)ROWS * EMB];
__device__ float g_k[(size_t)ROWS * EMB];
__device__ float g_v[(size_t)ROWS * EMB];
__device__ float g_att[(size_t)ROWS * EMB];
__device__ float g_haux[4][(size_t)ROWS * 96];
// int8 double-word encodings
__device__ signed char g_a1[(size_t)4 * ROWS * KP8];
__device__ signed char g_a0[(size_t)4 * ROWS * KP8];
__device__ signed char g_w1[(size_t)4 * 2048 * KP8];
__device__ signed char g_w0[(size_t)4 * 2048 * KP8];
__device__ float g_sa[4 * ROWS];
__device__ float g_sw[4 * 2048];

// ---------------------------------------------------------------------------
// helpers
// ---------------------------------------------------------------------------
__device__ __forceinline__ unsigned pack_bf2(__nv_bfloat16 a, __nv_bfloat16 b) {
    return (unsigned)__bfloat16_as_ushort(a) | ((unsigned)__bfloat16_as_ushort(b) << 16);
}
__device__ __forceinline__ void split_bf(float x, __nv_bfloat16& hi, __nv_bfloat16& lo) {
    hi = __float2bfloat16_rn(x);
    lo = __float2bfloat16_rn(x - __bfloat162float(hi));
}
__device__ __forceinline__ void mma_bf16(float* c, const unsigned* a, const unsigned* b) {
    asm volatile(
        "mma.sync.aligned.m16n8k16.row.col.f32.bf16.bf16.f32 "
        "{%0,%1,%2,%3}, {%4,%5,%6,%7}, {%8,%9}, {%0,%1,%2,%3};"
        : "+f"(c[0]), "+f"(c[1]), "+f"(c[2]), "+f"(c[3])
        : "r"(a[0]), "r"(a[1]), "r"(a[2]), "r"(a[3]), "r"(b[0]), "r"(b[1]));
}
__device__ __forceinline__ void mma_s8(int* c, const unsigned* a, const unsigned* b) {
    asm volatile(
        "mma.sync.aligned.m16n8k32.row.col.s32.s8.s8.s32 "
        "{%0,%1,%2,%3}, {%4,%5,%6,%7}, {%8,%9}, {%0,%1,%2,%3};"
        : "+r"(c[0]), "+r"(c[1]), "+r"(c[2]), "+r"(c[3])
        : "r"(a[0]), "r"(a[1]), "r"(a[2]), "r"(a[3]), "r"(b[0]), "r"(b[1]));
}
__device__ __forceinline__ void cp16(unsigned saddr, const void* g) {
    asm volatile("cp.async.cg.shared.global [%0], [%1], 16;" :: "r"(saddr), "l"(g) : "memory");
}
#define CP_COMMIT asm volatile("cp.async.commit_group;\n" ::: "memory")
__device__ __forceinline__ unsigned s2u(const void* p) {
    unsigned a;
    asm("{ .reg .u64 t; cvta.to.shared.u64 t, %1; cvt.u32.u64 %0, t; }" : "=r"(a) : "l"(p));
    return a;
}

// ---------------------------------------------------------------------------
// pack_w_i8: per output column n (and proj p), quantize [W|B|R] row into
// two int8 words with scale sw. KP8 stride, zero pad.
// ---------------------------------------------------------------------------
__global__ void pack_w_i8(
    const float* __restrict__ W0, const float* __restrict__ B0, const float* __restrict__ R0,
    const float* __restrict__ W1, const float* __restrict__ B1, const float* __restrict__ R1,
    const float* __restrict__ W2, const float* __restrict__ B2, const float* __restrict__ R2,
    const float* __restrict__ W3, const float* __restrict__ B3, const float* __restrict__ R3,
    signed char* __restrict__ w1, signed char* __restrict__ w0, float* __restrict__ sw)
{
    const int n = blockIdx.x, p = blockIdx.y, tid = threadIdx.x;
    const float* W = (p == 0) ? W0 : (p == 1) ? W1 : (p == 2) ? W2 : W3;
    const float* Bm = (p == 0) ? B0 : (p == 1) ? B1 : (p == 2) ? B2 : B3;
    const float* Rm = (p == 0) ? R0 : (p == 1) ? R1 : (p == 2) ? R2 : R3;

    __shared__ float red[256];
    float mx = 0.f;
    for (int k = tid; k < KAUG; k += 256) {
        float v = (k < EMB) ? W[(size_t)n * EMB + k]
                : (k < EMB + RLORA) ? Bm[(size_t)n * RLORA + (k - EMB)]
                : Rm[(size_t)n * NEXP_ + (k - EMB - RLORA)];
        mx = fmaxf(mx, fabsf(v));
    }
    red[tid] = mx; __syncthreads();
    for (int s = 128; s > 0; s >>= 1) {
        if (tid < s) red[tid] = fmaxf(red[tid], red[tid + s]);
        __syncthreads();
    }
    const float amax = red[0];
    const float inv = (amax > 0.f) ? 16256.f / amax : 0.f;
    if (tid == 0) sw[p * 2048 + n] = amax * (1.f / 16256.f);

    signed char* d1 = w1 + ((size_t)p * 2048 + n) * KP8;
    signed char* d0 = w0 + ((size_t)p * 2048 + n) * KP8;
    for (int k4 = tid * 4; k4 < KP8; k4 += 1024) {
        char4 o1, o0;
        signed char* p1 = (signed char*)&o1;
        signed char* p0 = (signed char*)&o0;
        #pragma unroll
        for (int j = 0; j < 4; j++) {
            int k = k4 + j;
            float v = 0.f;
            if (k < EMB)              v = W[(size_t)n * EMB + k];
            else if (k < EMB + RLORA) v = Bm[(size_t)n * RLORA + (k - EMB)];
            else if (k < KAUG)        v = Rm[(size_t)n * NEXP_ + (k - EMB - RLORA)];
            float qv = v * inv;
            int i1 = __float2int_rn(qv * 0.0078125f);
            int i0 = __float2int_rn(qv - 128.f * (float)i1);
            p1[j] = (signed char)i1;
            p0[j] = (signed char)i0;
        }
        *(char4*)(d1 + k4) = o1;
        *(char4*)(d0 + k4) = o0;
    }
}

// ---------------------------------------------------------------------------
// quant_act: per row, quantize augmented activation [x(2048) | haux(96) | 0]
// into two int8 words + row scale. grid (ROWS, nproj); plane = pbase+blockIdx.y
// ---------------------------------------------------------------------------
__global__ void quant_act(
    const float* __restrict__ act,
    const float* __restrict__ h0, const float* __restrict__ h1, const float* __restrict__ h2,
    signed char* __restrict__ a1b, signed char* __restrict__ a0b, float* __restrict__ sab,
    int pbase)
{
    const int row = blockIdx.x, p = blockIdx.y, tid = threadIdx.x;
    const float* h = (p == 0) ? h0 : (p == 1) ? h1 : h2;
    const int plane = pbase + p;
    const float* xr = act + (size_t)row * EMB;
    const float* hr = h + (size_t)row * 96;

    __shared__ float red[256];
    float mx = 0.f;
    for (int k = tid; k < KAUG; k += 256) {
        float v = (k < EMB) ? xr[k] : hr[k - EMB];
        mx = fmaxf(mx, fabsf(v));
    }
    red[tid] = mx; __syncthreads();
    for (int s = 128; s > 0; s >>= 1) {
        if (tid < s) red[tid] = fmaxf(red[tid], red[tid + s]);
        __syncthreads();
    }
    const float amax = red[0];
    const float inv = (amax > 0.f) ? 16256.f / amax : 0.f;
    if (tid == 0) sab[plane * ROWS + row] = amax * (1.f / 16256.f);

    signed char* d1 = a1b + ((size_t)plane * ROWS + row) * KP8;
    signed char* d0 = a0b + ((size_t)plane * ROWS + row) * KP8;
    for (int k4 = tid * 4; k4 < KP8; k4 += 1024) {
        char4 o1, o0;
        signed char* p1 = (signed char*)&o1;
        signed char* p0 = (signed char*)&o0;
        #pragma unroll
        for (int j = 0; j < 4; j++) {
            int k = k4 + j;
            float v = 0.f;
            if (k < EMB)       v = xr[k];
            else if (k < KAUG) v = hr[k - EMB];
            float qv = v * inv;
            int i1 = __float2int_rn(qv * 0.0078125f);
            int i0 = __float2int_rn(qv - 128.f * (float)i1);
            p1[j] = (signed char)i1;
            p0[j] = (signed char)i0;
        }
        *(char4*)(d1 + k4) = o1;
        *(char4*)(d0 + k4) = o0;
    }
}

// ---------------------------------------------------------------------------
// aux GEMM (fp32 out, stride 96): h[0:32]=silu(x@A^T), h[32:96]=silu(x@C^T)*mask
// ---------------------------------------------------------------------------
__global__ __launch_bounds__(256) void aux_gemm(
    const float* __restrict__ act, const float* __restrict__ mask,
    const float* __restrict__ A0, const float* __restrict__ C0,
    const float* __restrict__ A1, const float* __restrict__ C1,
    const float* __restrict__ A2, const float* __restrict__ C2,
    float* __restrict__ h0, float* __restrict__ h1, float* __restrict__ h2)
{
    __shared__ float As[16][132];
    __shared__ float Bs[16][100];

    const int proj = blockIdx.x;
    const int m0 = blockIdx.y * 128;
    const float* A = (proj == 0) ? A0 : ((proj == 1) ? A1 : A2);
    const float* C = (proj == 0) ? C0 : ((proj == 1) ? C1 : C2);
    float* hout    = (proj == 0) ? h0 : ((proj == 1) ? h1 : h2);

    const int tid = threadIdx.x;
    const int ty = tid >> 4, tx = tid & 15;

    float acc[8][6];
    #pragma unroll
    for (int i = 0; i < 8; i++)
        #pragma unroll
        for (int j = 0; j < 6; j++) acc[i][j] = 0.f;

    for (int k0 = 0; k0 < EMB; k0 += 16) {
        #pragma unroll
        for (int i = 0; i < 2; i++) {
            int lin = tid + 256 * i;
            int r = lin >> 2, c4 = (lin & 3) << 2;
            float4 va = *(const float4*)(act + (size_t)(m0 + r) * EMB + k0 + c4);
            As[c4 + 0][r] = va.x; As[c4 + 1][r] = va.y;
            As[c4 + 2][r] = va.z; As[c4 + 3][r] = va.w;
        }
        #pragma unroll
        for (int i = 0; i < 2; i++) {
            int lin = tid + 256 * i;
            if (lin < 384) {
                int r = lin >> 2, c4 = (lin & 3) << 2;
                const float* src = (r < 32) ? (A + (size_t)r * EMB)
                                            : (C + (size_t)(r - 32) * EMB);
                float4 vb = *(const float4*)(src + k0 + c4);
                Bs[c4 + 0][r] = vb.x; Bs[c4 + 1][r] = vb.y;
                Bs[c4 + 2][r] = vb.z; Bs[c4 + 3][r] = vb.w;
            }
        }
        __syncthreads();

        #pragma unroll
        for (int kk = 0; kk < 16; kk++) {
            float a[8], b[6];
            *(float4*)&a[0] = *(const float4*)&As[kk][ty * 8];
            *(float4*)&a[4] = *(const float4*)&As[kk][ty * 8 + 4];
            #pragma unroll
            for (int j = 0; j < 6; j++) b[j] = Bs[kk][tx * 6 + j];
            #pragma unroll
            for (int i = 0; i < 8; i++)
                #pragma unroll
                for (int j = 0; j < 6; j++)
                    acc[i][j] += a[i] * b[j];
        }
        __syncthreads();
    }

    #pragma unroll
    for (int i = 0; i < 8; i++) {
        int row = m0 + ty * 8 + i;
        #pragma unroll
        for (int j = 0; j < 6; j++) {
            int u = tx * 6 + j;
            float v = acc[i][j];
            float s = v / (1.f + expf(-v));
            if (u >= 32) s *= mask[(size_t)row * NEXP_ + (u - 32)];
            hout[(size_t)row * 96 + u] = s;
        }
    }
}

// ---------------------------------------------------------------------------
// int8 double-word projection GEMM. Block 128x64, 8 warps (4m x 2n),
// warp tile 32x32, m16n8k32 s8 mma, 3-stage cp.async pipeline.
// D = sa[m]*sw[n]*(16384*(A1W1) + 128*(A1W0 + A0W1)) + bias
// ---------------------------------------------------------------------------
#define PITCH   80
#define SA0_OFF 10240      // 128*80
#define SB1_OFF 20480
#define SB0_OFF 25600      // +64*80
#define STB8    30720
#define G8_SMEM (3 * STB8)

__global__ __launch_bounds__(256, 2) void gemm_i8(
    const signed char* __restrict__ a1, const signed char* __restrict__ a0,
    const float* __restrict__ sa,
    const signed char* __restrict__ w1, const signed char* __restrict__ w0,
    const float* __restrict__ sw,
    const float* __restrict__ bias, float* __restrict__ out)
{
    extern __shared__ char sm8[];
    const int tid = threadIdx.x;
    const int lane = tid & 31, wid = tid >> 5;
    const int l4 = lane >> 2, lk = lane & 3;
    const int warp_m = wid & 3, warp_n = wid >> 2;   // 4 x 2
    const int m0 = blockIdx.y * 128, n0 = blockIdx.x * 64;
    const unsigned dsm = s2u(sm8);

    int chi[2][4][4], cmid[2][4][4];
    #pragma unroll
    for (int mt = 0; mt < 2; mt++)
        #pragma unroll
        for (int nt = 0; nt < 4; nt++)
            #pragma unroll
            for (int i = 0; i < 4; i++) { chi[mt][nt][i] = 0; cmid[mt][nt][i] = 0; }

#define FILL8(STG, C) do {                                                      \
    unsigned sb_ = dsm + (STG) * STB8; int c_ = (C);                            \
    _Pragma("unroll")                                                           \
    for (int t_ = 0; t_ < 2; t_++) {                                            \
        int idx_ = tid * 2 + t_;                                                \
        int r_ = idx_ >> 2, ch_ = (idx_ & 3) * 16;                              \
        size_t go_ = (size_t)(m0 + r_) * KP8 + c_ * 64 + ch_;                   \
        cp16(sb_ + r_ * PITCH + ch_, a1 + go_);                                 \
        cp16(sb_ + SA0_OFF + r_ * PITCH + ch_, a0 + go_);                       \
    }                                                                           \
    {   int r_ = tid >> 2, ch_ = (tid & 3) * 16;                                \
        size_t go_ = (size_t)(n0 + r_) * KP8 + c_ * 64 + ch_;                   \
        cp16(sb_ + SB1_OFF + r_ * PITCH + ch_, w1 + go_);                       \
        cp16(sb_ + SB0_OFF + r_ * PITCH + ch_, w0 + go_);                       \
    }                                                                           \
} while (0)

    FILL8(0, 0); CP_COMMIT;
    FILL8(1, 1); CP_COMMIT;

    for (int c = 0; c < NCH; c++) {
        asm volatile("cp.async.wait_group 1;" ::: "memory");
        __syncthreads();

        int nf = c + 2;
        if (nf < NCH) FILL8(nf % 3, nf);
        CP_COMMIT;

        const char* sb = sm8 + (c % 3) * STB8;
        #pragma unroll
        for (int ks = 0; ks < 2; ks++) {
            unsigned fa1[2][4], fa0[2][4];
            #pragma unroll
            for (int mt = 0; mt < 2; mt++) {
                int rb = warp_m * 32 + mt * 16 + l4;
                const char* pr = sb + rb * PITCH + ks * 32 + lk * 4;
                fa1[mt][0] = *(const unsigned*)(pr);
                fa1[mt][1] = *(const unsigned*)(pr + 8 * PITCH);
                fa1[mt][2] = *(const unsigned*)(pr + 16);
                fa1[mt][3] = *(const unsigned*)(pr + 8 * PITCH + 16);
                fa0[mt][0] = *(const unsigned*)(pr + SA0_OFF);
                fa0[mt][1] = *(const unsigned*)(pr + SA0_OFF + 8 * PITCH);
                fa0[mt][2] = *(const unsigned*)(pr + SA0_OFF + 16);
                fa0[mt][3] = *(const unsigned*)(pr + SA0_OFF + 8 * PITCH + 16);
            }
            #pragma unroll
            for (int nt = 0; nt < 4; nt++) {
                int cb = warp_n * 32 + nt * 8 + l4;
                const char* pb = sb + SB1_OFF + cb * PITCH + ks * 32 + lk * 4;
                unsigned fb1[2], fb0[2];
                fb1[0] = *(const unsigned*)(pb);
                fb1[1] = *(const unsigned*)(pb + 16);
                fb0[0] = *(const unsigned*)(pb + (SB0_OFF - SB1_OFF));
                fb0[1] = *(const unsigned*)(pb + (SB0_OFF - SB1_OFF) + 16);
                #pragma unroll
                for (int mt = 0; mt < 2; mt++) {
                    mma_s8(chi[mt][nt],  fa1[mt], fb1);
                    mma_s8(cmid[mt][nt], fa1[mt], fb0);
                    mma_s8(cmid[mt][nt], fa0[mt], fb1);
                }
            }
        }
    }
#undef FILL8

    // epilogue
    #pragma unroll
    for (int mt = 0; mt < 2; mt++) {
        int r0 = m0 + warp_m * 32 + mt * 16 + l4;
        float s_a0 = sa[r0], s_a1 = sa[r0 + 8];
        #pragma unroll
        for (int nt = 0; nt < 4; nt++) {
            int col = n0 + warp_n * 32 + nt * 8 + 2 * lk;
            float w0s = sw[col], w1s = sw[col + 1];
            float b0v = 0.f, b1v = 0.f;
            if (bias) { b0v = bias[col]; b1v = bias[col + 1]; }
            float d0 = s_a0 * w0s * (16384.f * (float)chi[mt][nt][0] + 128.f * (float)cmid[mt][nt][0]) + b0v;
            float d1 = s_a0 * w1s * (16384.f * (float)chi[mt][nt][1] + 128.f * (float)cmid[mt][nt][1]) + b1v;
            float d2 = s_a1 * w0s * (16384.f * (float)chi[mt][nt][2] + 128.f * (float)cmid[mt][nt][2]) + b0v;
            float d3 = s_a1 * w1s * (16384.f * (float)chi[mt][nt][3] + 128.f * (float)cmid[mt][nt][3]) + b1v;
            *(float2*)(out + (size_t)r0 * EMB + col)       = make_float2(d0, d1);
            *(float2*)(out + (size_t)(r0 + 8) * EMB + col) = make_float2(d2, d3);
        }
    }
}

// ---------------------------------------------------------------------------
// RoPE (in-place on q and k)
// ---------------------------------------------------------------------------
__global__ void rope_kernel(float* __restrict__ q, float* __restrict__ k)
{
    int idx = blockIdx.x * blockDim.x + threadIdx.x;
    if (idx >= ROWS * NHEAD * 64) return;
    int j   = idx & 63;
    int h   = (idx >> 6) & 15;
    int row = idx >> 10;
    int s   = row & (SEQ - 1);

    float e   = (float)(2 * j) * (1.0f / 128.0f);
    float inv = powf(10000.0f, -e);
    float ang = (float)s * inv;
    float sn, cs;
    sincosf(ang, &sn, &cs);

    size_t base = (size_t)row * EMB + h * DHEAD + j;
    float x1 = q[base], x2 = q[base + 64];
    q[base]      = x1 * cs - x2 * sn;
    q[base + 64] = x2 * cs + x1 * sn;
    x1 = k[base]; x2 = k[base + 64];
    k[base]      = x1 * cs - x2 * sn;
    k[base + 64] = x2 * cs + x1 * sn;
}

// ---------------------------------------------------------------------------
// Causal flash attention on tensor cores (split-bf16 mma.sync) — as R5.
// ---------------------------------------------------------------------------
#define KPP 68
#define VPP 136
#define FA2_SMEM ((64 * KPP * 2 + 32 * VPP * 2) * 4)

__global__ __launch_bounds__(256) void flash_mma(
    const float* __restrict__ q, const float* __restrict__ k,
    const float* __restrict__ v, float* __restrict__ o)
{
    extern __shared__ unsigned sw_[];
    unsigned* Kph = sw_;
    unsigned* Kpl = Kph + 64 * KPP;
    unsigned* Vph = Kpl + 64 * KPP;
    unsigned* Vpl = Vph + 32 * VPP;

    const int tid = threadIdx.x;
    const int lane = tid & 31, wm = tid >> 5;
    const int l4 = lane >> 2, lk = lane & 3;
    const int iblk = (int)gridDim.x - 1 - (int)blockIdx.x;
    const int bh = blockIdx.y;
    const int b = bh >> 4, h = bh & 15;
    const size_t rowbase = (size_t)b * SEQ;
    const int m0 = iblk * 128;
    const float scale = 0.08838834764831845f;

    unsigned qh[8][4], ql[8][4];
    {
        const int r0 = m0 + wm * 16 + l4;
        #pragma unroll
        for (int s = 0; s < 8; s++) {
            #pragma unroll
            for (int f = 0; f < 4; f++) {
                int r = r0 + ((f & 1) ? 8 : 0);
                int d = 16 * s + 2 * lk + ((f & 2) ? 8 : 0);
                float2 qv = *(const float2*)(q + (rowbase + r) * EMB + h * DHEAD + d);
                float x = qv.x * scale, y = qv.y * scale;
                __nv_bfloat16 hx, lx, hy, ly;
                split_bf(x, hx, lx); split_bf(y, hy, ly);
                qh[s][f] = pack_bf2(hx, hy);
                ql[s][f] = pack_bf2(lx, ly);
            }
        }
    }

    float mr0 = -1e30f, mr1 = -1e30f, lr0 = 0.f, lr1 = 0.f;
    float oacc[16][4];
    #pragma unroll
    for (int nt = 0; nt < 16; nt++)
        #pragma unroll
        for (int i = 0; i < 4; i++) oacc[nt][i] = 0.f;

    const int ntiles = 2 * iblk + 2;
    for (int j = 0; j < ntiles; j++) {
        #pragma unroll
        for (int i = 0; i < 16; i++) {
            int lin = tid + 256 * i;
            int n = lin >> 6, dw = lin & 63;
            float2 kv = *(const float2*)(k + (rowbase + j * 64 + n) * EMB + h * DHEAD + 2 * dw);
            __nv_bfloat16 hx, lx, hy, ly;
            split_bf(kv.x, hx, lx); split_bf(kv.y, hy, ly);
            Kph[n * KPP + dw] = pack_bf2(hx, hy);
            Kpl[n * KPP + dw] = pack_bf2(lx, ly);
        }
        #pragma unroll
        for (int i = 0; i < 16; i++) {
            int lin = tid + 256 * i;
            int kw = lin >> 7, nn = lin & 127;
            size_t rbase = (rowbase + j * 64 + 2 * kw) * EMB + h * DHEAD + nn;
            float v0 = v[rbase];
            float v1 = v[rbase + EMB];
            __nv_bfloat16 h0, l0, h1, l1;
            split_bf(v0, h0, l0); split_bf(v1, h1, l1);
            Vph[kw * VPP + nn] = pack_bf2(h0, h1);
            Vpl[kw * VPP + nn] = pack_bf2(l0, l1);
        }
        __syncthreads();

        float sacc[8][4];
        #pragma unroll
        for (int nt = 0; nt < 8; nt++)
            #pragma unroll
            for (int i = 0; i < 4; i++) sacc[nt][i] = 0.f;

        #pragma unroll
        for (int s = 0; s < 8; s++) {
            #pragma unroll
            for (int nt = 0; nt < 8; nt++) {
                int kr = (nt * 8 + l4) * KPP + 8 * s + lk;
                unsigned b_hi[2], b_lo[2];
                b_hi[0] = Kph[kr];
                b_hi[1] = Kph[kr + 4];
                b_lo[0] = Kpl[kr];
                b_lo[1] = Kpl[kr + 4];
                mma_bf16(sacc[nt], qh[s], b_hi);
                mma_bf16(sacc[nt], qh[s], b_lo);
                mma_bf16(sacc[nt], ql[s], b_hi);
            }
        }

        if (j >= 2 * iblk) {
            int row0 = m0 + wm * 16 + l4;
            #pragma unroll
            for (int nt = 0; nt < 8; nt++) {
                int col = j * 64 + nt * 8 + 2 * lk;
                if (col     > row0)     sacc[nt][0] = -1e30f;
                if (col + 1 > row0)     sacc[nt][1] = -1e30f;
                if (col     > row0 + 8) sacc[nt][2] = -1e30f;
                if (col + 1 > row0 + 8) sacc[nt][3] = -1e30f;
            }
        }

        float mx0 = -1e30f, mx1 = -1e30f;
        #pragma unroll
        for (int nt = 0; nt < 8; nt++) {
            mx0 = fmaxf(mx0, fmaxf(sacc[nt][0], sacc[nt][1]));
            mx1 = fmaxf(mx1, fmaxf(sacc[nt][2], sacc[nt][3]));
        }
        mx0 = fmaxf(mx0, __shfl_xor_sync(0xffffffffu, mx0, 1));
        mx0 = fmaxf(mx0, __shfl_xor_sync(0xffffffffu, mx0, 2));
        mx1 = fmaxf(mx1, __shfl_xor_sync(0xffffffffu, mx1, 1));
        mx1 = fmaxf(mx1, __shfl_xor_sync(0xffffffffu, mx1, 2));

        float mn0 = fmaxf(mr0, mx0), mn1 = fmaxf(mr1, mx1);
        float al0 = __expf(mr0 - mn0), al1 = __expf(mr1 - mn1);
        mr0 = mn0; mr1 = mn1;

        unsigned ph01[8], pl01[8], ph23[8], pl23[8];
        float rs0 = 0.f, rs1 = 0.f;
        #pragma unroll
        for (int nt = 0; nt < 8; nt++) {
            float p0 = __expf(sacc[nt][0] - mn0);
            float p1 = __expf(sacc[nt][1] - mn0);
            float p2 = __expf(sacc[nt][2] - mn1);
            float p3 = __expf(sacc[nt][3] - mn1);
            rs0 += p0 + p1; rs1 += p2 + p3;
            __nv_bfloat16 h0, l0, h1, l1;
            split_bf(p0, h0, l0); split_bf(p1, h1, l1);
            ph01[nt] = pack_bf2(h0, h1); pl01[nt] = pack_bf2(l0, l1);
            split_bf(p2, h0, l0); split_bf(p3, h1, l1);
            ph23[nt] = pack_bf2(h0, h1); pl23[nt] = pack_bf2(l0, l1);
        }
        rs0 += __shfl_xor_sync(0xffffffffu, rs0, 1);
        rs0 += __shfl_xor_sync(0xffffffffu, rs0, 2);
        rs1 += __shfl_xor_sync(0xffffffffu, rs1, 1);
        rs1 += __shfl_xor_sync(0xffffffffu, rs1, 2);
        lr0 = lr0 * al0 + rs0;
        lr1 = lr1 * al1 + rs1;

        #pragma unroll
        for (int nt = 0; nt < 16; nt++) {
            oacc[nt][0] *= al0; oacc[nt][1] *= al0;
            oacc[nt][2] *= al1; oacc[nt][3] *= al1;
        }

        #pragma unroll
        for (int t = 0; t < 4; t++) {
            unsigned pa_h[4], pa_l[4];
            pa_h[0] = ph01[2 * t];     pa_l[0] = pl01[2 * t];
            pa_h[1] = ph23[2 * t];     pa_l[1] = pl23[2 * t];
            pa_h[2] = ph01[2 * t + 1]; pa_l[2] = pl01[2 * t + 1];
            pa_h[3] = ph23[2 * t + 1]; pa_l[3] = pl23[2 * t + 1];
            #pragma unroll
            for (int nt = 0; nt < 16; nt++) {
                int vr = (8 * t + lk) * VPP + nt * 8 + l4;
                unsigned b_hi[2], b_lo[2];
                b_hi[0] = Vph[vr];
                b_hi[1] = Vph[vr + 4 * VPP];
                b_lo[0] = Vpl[vr];
                b_lo[1] = Vpl[vr + 4 * VPP];
                mma_bf16(oacc[nt], pa_h, b_hi);
                mma_bf16(oacc[nt], pa_l, b_hi);
                mma_bf16(oacc[nt], pa_h, b_lo);
            }
        }
        __syncthreads();
    }

    float il0 = 1.f / lr0, il1 = 1.f / lr1;
    int row0 = m0 + wm * 16 + l4;
    #pragma unroll
    for (int nt = 0; nt < 16; nt++) {
        int col = h * DHEAD + nt * 8 + 2 * lk;
        float2 o0 = make_float2(oacc[nt][0] * il0, oacc[nt][1] * il0);
        float2 o1 = make_float2(oacc[nt][2] * il1, oacc[nt][3] * il1);
        *(float2*)(o + (rowbase + row0) * EMB + col)     = o0;
        *(float2*)(o + (rowbase + row0 + 8) * EMB + col) = o1;
    }
}

// ---------------------------------------------------------------------------
extern "C" void kernel_launch(void* const* d_in, const int* in_sizes, int n_in,
                              void* d_out, int out_size)
{
    const float* x    = (const float*)d_in[0];
    const float* mask = (const float*)d_in[1];
    const float* Wq = (const float*)d_in[2];  const float* bq = (const float*)d_in[3];
    const float* Aq = (const float*)d_in[4];  const float* Bq = (const float*)d_in[5];
    const float* Cq = (const float*)d_in[6];  const float* Rq = (const float*)d_in[7];
    const float* Wk = (const float*)d_in[8];  const float* bk = (const float*)d_in[9];
    const float* Ak = (const float*)d_in[10]; const float* Bk = (const float*)d_in[11];
    const float* Ck = (const float*)d_in[12]; const float* Rk = (const float*)d_in[13];
    const float* Wv = (const float*)d_in[14]; const float* bv = (const float*)d_in[15];
    const float* Av = (const float*)d_in[16]; const float* Bv = (const float*)d_in[17];
    const float* Cv = (const float*)d_in[18]; const float* Rv = (const float*)d_in[19];
    const float* Wo = (const float*)d_in[20]; const float* Ao = (const float*)d_in[21];
    const float* Bo = (const float*)d_in[22]; const float* Co = (const float*)d_in[23];
    const float* Ro = (const float*)d_in[24];

    float *q, *k, *v, *att, *hx, *sav, *swv;
    signed char *a1, *a0, *w1, *w0;
    cudaGetSymbolAddress((void**)&q,   g_q);
    cudaGetSymbolAddress((void**)&k,   g_k);
    cudaGetSymbolAddress((void**)&v,   g_v);
    cudaGetSymbolAddress((void**)&att, g_att);
    cudaGetSymbolAddress((void**)&hx,  g_haux);
    cudaGetSymbolAddress((void**)&a1,  g_a1);
    cudaGetSymbolAddress((void**)&a0,  g_a0);
    cudaGetSymbolAddress((void**)&w1,  g_w1);
    cudaGetSymbolAddress((void**)&w0,  g_w0);
    cudaGetSymbolAddress((void**)&sav, g_sa);
    cudaGetSymbolAddress((void**)&swv, g_sw);

    float* hq = hx;
    float* hk = hx + (size_t)ROWS * 96;
    float* hv = hx + (size_t)ROWS * 96 * 2;
    float* ho = hx + (size_t)ROWS * 96 * 3;

    cudaFuncSetAttribute(flash_mma,
                         cudaFuncAttributeMaxDynamicSharedMemorySize, FA2_SMEM);
    cudaFuncSetAttribute(gemm_i8,
                         cudaFuncAttributeMaxDynamicSharedMemorySize, G8_SMEM);

    const size_t APL = (size_t)ROWS * KP8;
    const size_t WPL = (size_t)2048 * KP8;
    dim3 ggrid(EMB / 64, ROWS / 128);   // (32, 32)

    // quantize weights (one logical pass; graph replays it, still correct)
    pack_w_i8<<<dim3(2048, 4), 256>>>(Wq, Bq, Rq, Wk, Bk, Rk, Wv, Bv, Rv,
                                      Wo, Bo, Ro, w1, w0, swv);
    // aux terms for q/k/v
    aux_gemm<<<dim3(3, ROWS / 128), 256>>>(x, mask, Aq, Cq, Ak, Ck, Av, Cv, hq, hk, hv);
    // quantize activations (per projection, augmented rows)
    quant_act<<<dim3(ROWS, 3), 256>>>(x, hq, hk, hv, a1, a0, sav, 0);
    // projections (int8 tensor cores)
    gemm_i8<<<ggrid, 256, G8_SMEM>>>(a1,           a0,           sav,
                                     w1,           w0,           swv,           bq, q);
    gemm_i8<<<ggrid, 256, G8_SMEM>>>(a1 + APL,     a0 + APL,     sav + ROWS,
                                     w1 + WPL,     w0 + WPL,     swv + 2048,    bk, k);
    gemm_i8<<<ggrid, 256, G8_SMEM>>>(a1 + 2 * APL, a0 + 2 * APL, sav + 2 * ROWS,
                                     w1 + 2 * WPL, w0 + 2 * WPL, swv + 2 * 2048, bv, v);
    // rope
    rope_kernel<<<(ROWS * NHEAD * 64 + 255) / 256, 256>>>(q, k);
    // flash attention
    flash_mma<<<dim3(SEQ / 128, BATCH * NHEAD), 256, FA2_SMEM>>>(q, k, v, att);
    // output projection
    aux_gemm<<<dim3(1, ROWS / 128), 256>>>(att, mask, Ao, Co, Ao, Co, Ao, Co, ho, ho, ho);
    quant_act<<<dim3(ROWS, 1), 256>>>(att, ho, ho, ho, a1, a0, sav, 3);
    gemm_i8<<<ggrid, 256, G8_SMEM>>>(a1 + 3 * APL, a0 + 3 * APL, sav + 3 * ROWS,
                                     w1 + 3 * WPL, w0 + 3 * WPL, swv + 3 * 2048,
                                     nullptr, (float*)d_out);
}

// round 10
// speedup vs baseline: 1.6843x; 1.6843x over previous
#include <cuda_runtime.h>
#include <cuda_bf16.h>
#include <cuda_fp16.h>
#include <cstdint>
#include <math.h>

#define BATCH 2
#define SEQ   2048
#define EMB   2048
#define NHEAD 16
#define DHEAD 128
#define NEXP_ 64
#define RLORA 32
#define ROWS  4096
#define KAUG  2144

// ---------------- scratch ----------------
__device__ float g_q[(size_t)ROWS * EMB];
__device__ float g_k[(size_t)ROWS * EMB];
__device__ float g_v[(size_t)ROWS * EMB];
__device__ float g_att[(size_t)ROWS * EMB];
__device__ float g_haux[4][(size_t)ROWS * 96];
// packed tiles for flash: K bf16 hi/lo along d-pairs, V fp16 hi/lo along k-pairs
__device__ unsigned g_kph[(size_t)32 * 2048 * 64];
__device__ unsigned g_kpl[(size_t)32 * 2048 * 64];
__device__ unsigned g_vph[(size_t)32 * 1024 * 128];
__device__ unsigned g_vpl[(size_t)32 * 1024 * 128];

// ---------------- helpers ----------------
__device__ __forceinline__ unsigned pack_bf2(__nv_bfloat16 a, __nv_bfloat16 b) {
    return (unsigned)__bfloat16_as_ushort(a) | ((unsigned)__bfloat16_as_ushort(b) << 16);
}
__device__ __forceinline__ void split_bf(float x, __nv_bfloat16& hi, __nv_bfloat16& lo) {
    hi = __float2bfloat16_rn(x);
    lo = __float2bfloat16_rn(x - __bfloat162float(hi));
}
__device__ __forceinline__ unsigned pack_h2(__half a, __half b) {
    __half2 t = __halves2half2(a, b);
    return *(unsigned*)&t;
}
// fp16 split for GEMM: hi + lo*2^-12, lo stored pre-scaled by 4096
__device__ __forceinline__ void split_h(float x, __half& hi, __half& lo) {
    hi = __float2half_rn(x);
    lo = __float2half_rn((x - __half2float(hi)) * 4096.f);
}
// fp16 split for V: hi + lo (unscaled; lo magnitude ~2^-12*v stays fp16-normal)
__device__ __forceinline__ void split_h_plain(float x, __half& hi, __half& lo) {
    hi = __float2half_rn(x);
    lo = __float2half_rn(x - __half2float(hi));
}
__device__ __forceinline__ void mma_bf16(float* c, const unsigned* a, const unsigned* b) {
    asm volatile(
        "mma.sync.aligned.m16n8k16.row.col.f32.bf16.bf16.f32 "
        "{%0,%1,%2,%3}, {%4,%5,%6,%7}, {%8,%9}, {%0,%1,%2,%3};"
        : "+f"(c[0]), "+f"(c[1]), "+f"(c[2]), "+f"(c[3])
        : "r"(a[0]), "r"(a[1]), "r"(a[2]), "r"(a[3]), "r"(b[0]), "r"(b[1]));
}
__device__ __forceinline__ void mma_f16_f32(float* c, const unsigned* a, const unsigned* b) {
    asm volatile(
        "mma.sync.aligned.m16n8k16.row.col.f32.f16.f16.f32 "
        "{%0,%1,%2,%3}, {%4,%5,%6,%7}, {%8,%9}, {%0,%1,%2,%3};"
        : "+f"(c[0]), "+f"(c[1]), "+f"(c[2]), "+f"(c[3])
        : "r"(a[0]), "r"(a[1]), "r"(a[2]), "r"(a[3]), "r"(b[0]), "r"(b[1]));
}
__device__ __forceinline__ void mma_f16_f16(unsigned* c, const unsigned* a, const unsigned* b) {
    asm volatile(
        "mma.sync.aligned.m16n8k16.row.col.f16.f16.f16.f16 "
        "{%0,%1}, {%2,%3,%4,%5}, {%6,%7}, {%0,%1};"
        : "+r"(c[0]), "+r"(c[1])
        : "r"(a[0]), "r"(a[1]), "r"(a[2]), "r"(a[3]), "r"(b[0]), "r"(b[1]));
}

// ---------------------------------------------------------------------------
// aux GEMM: h[0:32]=silu(x@A^T), h[32:96]=silu(x@C^T)*mask
// ---------------------------------------------------------------------------
__global__ __launch_bounds__(256) void aux_gemm(
    const float* __restrict__ act, const float* __restrict__ mask,
    const float* __restrict__ A0, const float* __restrict__ C0,
    const float* __restrict__ A1, const float* __restrict__ C1,
    const float* __restrict__ A2, const float* __restrict__ C2,
    float* __restrict__ h0, float* __restrict__ h1, float* __restrict__ h2)
{
    __shared__ float As[16][132];
    __shared__ float Bs[16][100];

    const int proj = blockIdx.x;
    const int m0 = blockIdx.y * 128;
    const float* A = (proj == 0) ? A0 : ((proj == 1) ? A1 : A2);
    const float* C = (proj == 0) ? C0 : ((proj == 1) ? C1 : C2);
    float* hout    = (proj == 0) ? h0 : ((proj == 1) ? h1 : h2);

    const int tid = threadIdx.x;
    const int ty = tid >> 4, tx = tid & 15;

    float acc[8][6];
    #pragma unroll
    for (int i = 0; i < 8; i++)
        #pragma unroll
        for (int j = 0; j < 6; j++) acc[i][j] = 0.f;

    for (int k0 = 0; k0 < EMB; k0 += 16) {
        #pragma unroll
        for (int i = 0; i < 2; i++) {
            int lin = tid + 256 * i;
            int r = lin >> 2, c4 = (lin & 3) << 2;
            float4 va = *(const float4*)(act + (size_t)(m0 + r) * EMB + k0 + c4);
            As[c4 + 0][r] = va.x; As[c4 + 1][r] = va.y;
            As[c4 + 2][r] = va.z; As[c4 + 3][r] = va.w;
        }
        #pragma unroll
        for (int i = 0; i < 2; i++) {
            int lin = tid + 256 * i;
            if (lin < 384) {
                int r = lin >> 2, c4 = (lin & 3) << 2;
                const float* src = (r < 32) ? (A + (size_t)r * EMB)
                                            : (C + (size_t)(r - 32) * EMB);
                float4 vb = *(const float4*)(src + k0 + c4);
                Bs[c4 + 0][r] = vb.x; Bs[c4 + 1][r] = vb.y;
                Bs[c4 + 2][r] = vb.z; Bs[c4 + 3][r] = vb.w;
            }
        }
        __syncthreads();

        #pragma unroll
        for (int kk = 0; kk < 16; kk++) {
            float a[8], b[6];
            *(float4*)&a[0] = *(const float4*)&As[kk][ty * 8];
            *(float4*)&a[4] = *(const float4*)&As[kk][ty * 8 + 4];
            #pragma unroll
            for (int j = 0; j < 6; j++) b[j] = Bs[kk][tx * 6 + j];
            #pragma unroll
            for (int i = 0; i < 8; i++)
                #pragma unroll
                for (int j = 0; j < 6; j++)
                    acc[i][j] += a[i] * b[j];
        }
        __syncthreads();
    }

    #pragma unroll
    for (int i = 0; i < 8; i++) {
        int row = m0 + ty * 8 + i;
        #pragma unroll
        for (int j = 0; j < 6; j++) {
            int u = tx * 6 + j;
            float v = acc[i][j];
            float s = v / (1.f + expf(-v));
            if (u >= 32) s *= mask[(size_t)row * NEXP_ + (u - 32)];
            hout[(size_t)row * 96 + u] = s;
        }
    }
}

// ---------------------------------------------------------------------------
// K-augmented GEMM, fp16 split: hi*hi -> f32-acc mma, crosses -> f16-acc mma
// (residuals pre-scaled x4096). Block 128x64, 8 warps (4m x 2n), warp 32x32.
// ---------------------------------------------------------------------------
__global__ __launch_bounds__(256, 2) void gemm_f16(
    const float* __restrict__ act, const float* __restrict__ haux,
    const float* __restrict__ Wd,  const float* __restrict__ Bl,
    const float* __restrict__ Rr,  const float* __restrict__ bias,
    float* __restrict__ out)
{
    __shared__ unsigned Ah[128][20], Al[128][20];
    __shared__ unsigned Bh[64][20],  Blo[64][20];

    const int tid = threadIdx.x;
    const int lane = tid & 31, wid = tid >> 5;
    const int l4 = lane >> 2, lk = lane & 3;
    const int warp_m = wid & 3, warp_n = wid >> 2;
    const int m0 = blockIdx.y * 128, n0 = blockIdx.x * 64;

    float c[2][4][4];
    unsigned c2[2][4][2];
    #pragma unroll
    for (int mt = 0; mt < 2; mt++)
        #pragma unroll
        for (int nt = 0; nt < 4; nt++) {
            #pragma unroll
            for (int i = 0; i < 4; i++) c[mt][nt][i] = 0.f;
            c2[mt][nt][0] = 0u; c2[mt][nt][1] = 0u;
        }

    for (int k0 = 0; k0 < KAUG; k0 += 32) {
        const float* asrc; int lda, kof;
        if (k0 < EMB) { asrc = act;  lda = EMB; kof = k0; }
        else          { asrc = haux; lda = 96;  kof = k0 - EMB; }

        const float* wsrc; int ldw, kofw;
        if (k0 < EMB)              { wsrc = Wd; ldw = EMB;   kofw = k0; }
        else if (k0 < EMB + RLORA) { wsrc = Bl; ldw = RLORA; kofw = k0 - EMB; }
        else                       { wsrc = Rr; ldw = NEXP_; kofw = k0 - EMB - RLORA; }

        #pragma unroll
        for (int i = 0; i < 4; i++) {
            int lin = tid + 256 * i;
            int r = lin >> 3, c4 = (lin & 7) << 2;
            float4 va = *(const float4*)(asrc + (size_t)(m0 + r) * lda + kof + c4);
            __half hx, lx, hy, ly, hz, lz, hw, lw;
            split_h(va.x, hx, lx); split_h(va.y, hy, ly);
            split_h(va.z, hz, lz); split_h(va.w, hw, lw);
            int wofs = c4 >> 1;
            *(uint2*)&Ah[r][wofs] = make_uint2(pack_h2(hx, hy), pack_h2(hz, hw));
            *(uint2*)&Al[r][wofs] = make_uint2(pack_h2(lx, ly), pack_h2(lz, lw));
        }
        #pragma unroll
        for (int i = 0; i < 2; i++) {
            int lin = tid + 256 * i;
            int r = lin >> 3, c4 = (lin & 7) << 2;
            float4 vb = *(const float4*)(wsrc + (size_t)(n0 + r) * ldw + kofw + c4);
            __half hx, lx, hy, ly, hz, lz, hw, lw;
            split_h(vb.x, hx, lx); split_h(vb.y, hy, ly);
            split_h(vb.z, hz, lz); split_h(vb.w, hw, lw);
            int wofs = c4 >> 1;
            *(uint2*)&Bh[r][wofs]  = make_uint2(pack_h2(hx, hy), pack_h2(hz, hw));
            *(uint2*)&Blo[r][wofs] = make_uint2(pack_h2(lx, ly), pack_h2(lz, lw));
        }
        __syncthreads();

        #pragma unroll
        for (int ks = 0; ks < 2; ks++) {
            const int kw = ks * 8;
            unsigned ah[2][4], al[2][4];
            #pragma unroll
            for (int mt = 0; mt < 2; mt++) {
                int rb = warp_m * 32 + mt * 16 + l4;
                ah[mt][0] = Ah[rb][kw + lk];
                ah[mt][1] = Ah[rb + 8][kw + lk];
                ah[mt][2] = Ah[rb][kw + 4 + lk];
                ah[mt][3] = Ah[rb + 8][kw + 4 + lk];
                al[mt][0] = Al[rb][kw + lk];
                al[mt][1] = Al[rb + 8][kw + lk];
                al[mt][2] = Al[rb][kw + 4 + lk];
                al[mt][3] = Al[rb + 8][kw + 4 + lk];
            }
            #pragma unroll
            for (int nt = 0; nt < 4; nt++) {
                int cb = warp_n * 32 + nt * 8 + l4;
                unsigned bh[2], bl[2];
                bh[0] = Bh[cb][kw + lk];
                bh[1] = Bh[cb][kw + 4 + lk];
                bl[0] = Blo[cb][kw + lk];
                bl[1] = Blo[cb][kw + 4 + lk];
                #pragma unroll
                for (int mt = 0; mt < 2; mt++) {
                    mma_f16_f32(c[mt][nt], ah[mt], bh);     // hi*hi, f32 acc
                    mma_f16_f16(c2[mt][nt], ah[mt], bl);    // hi*lo', f16 acc
                    mma_f16_f16(c2[mt][nt], al[mt], bh);    // lo'*hi, f16 acc
                }
            }
        }
        __syncthreads();
    }

    const float rs = 1.f / 4096.f;
    #pragma unroll
    for (int mt = 0; mt < 2; mt++) {
        int r0 = m0 + warp_m * 32 + mt * 16 + l4;
        #pragma unroll
        for (int nt = 0; nt < 4; nt++) {
            int col = n0 + warp_n * 32 + nt * 8 + 2 * lk;
            __half2 cr01 = *(__half2*)&c2[mt][nt][0];
            __half2 cr23 = *(__half2*)&c2[mt][nt][1];
            float b0 = 0.f, b1 = 0.f;
            if (bias) { b0 = bias[col]; b1 = bias[col + 1]; }
            float d0 = c[mt][nt][0] + __low2float(cr01)  * rs + b0;
            float d1 = c[mt][nt][1] + __high2float(cr01) * rs + b1;
            float d2 = c[mt][nt][2] + __low2float(cr23)  * rs + b0;
            float d3 = c[mt][nt][3] + __high2float(cr23) * rs + b1;
            *(float2*)(out + (size_t)r0 * EMB + col)       = make_float2(d0, d1);
            *(float2*)(out + (size_t)(r0 + 8) * EMB + col) = make_float2(d2, d3);
        }
    }
}

// ---------------------------------------------------------------------------
// rope_pack: rope q in-place (fp32); rope k -> packed bf16 hi/lo, K[bh][s][dw]
// ---------------------------------------------------------------------------
__global__ void rope_pack(float* __restrict__ q, const float* __restrict__ k,
                          unsigned* __restrict__ kph, unsigned* __restrict__ kpl)
{
    int idx = blockIdx.x * blockDim.x + threadIdx.x;   // ROWS*16*32
    if (idx >= ROWS * NHEAD * 32) return;
    int jj  = idx & 31;
    int h   = (idx >> 5) & 15;
    int row = idx >> 9;
    int s   = row & (SEQ - 1);
    int b   = row >> 11;

    float sn[2], cs[2];
    #pragma unroll
    for (int t = 0; t < 2; t++) {
        int d = 2 * jj + t;
        float e = (float)(2 * d) * (1.0f / 128.0f);
        float inv = powf(10000.0f, -e);
        sincosf((float)s * inv, &sn[t], &cs[t]);
    }

    size_t base = (size_t)row * EMB + h * DHEAD;
    float qlo[2], qhi2[2], klo[2], khi2[2];
    #pragma unroll
    for (int t = 0; t < 2; t++) {
        int d = 2 * jj + t;
        float x1 = q[base + d], x2 = q[base + d + 64];
        qlo[t]  = x1 * cs[t] - x2 * sn[t];
        qhi2[t] = x2 * cs[t] + x1 * sn[t];
        float y1 = k[base + d], y2 = k[base + d + 64];
        klo[t]  = y1 * cs[t] - y2 * sn[t];
        khi2[t] = y2 * cs[t] + y1 * sn[t];
    }
    #pragma unroll
    for (int t = 0; t < 2; t++) {
        q[base + 2 * jj + t]      = qlo[t];
        q[base + 2 * jj + t + 64] = qhi2[t];
    }
    int bh = b * NHEAD + h;
    size_t kbase = ((size_t)bh * SEQ + s) * 64;
    __nv_bfloat16 h0, l0, h1, l1;
    split_bf(klo[0], h0, l0); split_bf(klo[1], h1, l1);
    kph[kbase + jj] = pack_bf2(h0, h1);
    kpl[kbase + jj] = pack_bf2(l0, l1);
    split_bf(khi2[0], h0, l0); split_bf(khi2[1], h1, l1);
    kph[kbase + jj + 32] = pack_bf2(h0, h1);
    kpl[kbase + jj + 32] = pack_bf2(l0, l1);
}

// ---------------------------------------------------------------------------
// vpack: V[bh][kw][nn] = pack_f16(V[s=2kw][nn], V[2kw+1][nn]) fp16 hi/lo
// ---------------------------------------------------------------------------
__global__ void vpack(const float* __restrict__ v,
                      unsigned* __restrict__ vph, unsigned* __restrict__ vpl)
{
    int idx = blockIdx.x * blockDim.x + threadIdx.x;   // 32*1024*128
    if (idx >= 32 * 1024 * 128) return;
    int nn = idx & 127;
    int kw = (idx >> 7) & 1023;
    int bh = idx >> 17;
    int b = bh >> 4, h = bh & 15;
    size_t addr = ((size_t)(b * SEQ + 2 * kw)) * EMB + h * DHEAD + nn;
    float v0 = v[addr], v1 = v[addr + EMB];
    __half h0, l0, h1, l1;
    split_h_plain(v0, h0, l0); split_h_plain(v1, h1, l1);
    vph[idx] = pack_h2(h0, h1);
    vpl[idx] = pack_h2(l0, l1);
}

// ---------------------------------------------------------------------------
// Flash attention: QK 3-term bf16 (prepacked K), PV 2-term fp16
// (p single fp16 x V fp16 hi + lo), both f32 accumulate.
// ---------------------------------------------------------------------------
#define KPP 68
#define VPP 136
#define FA2_SMEM ((64 * KPP * 2 + 32 * VPP * 2) * 4)

__global__ __launch_bounds__(256) void flash_mma(
    const float* __restrict__ q,
    const unsigned* __restrict__ kph, const unsigned* __restrict__ kpl,
    const unsigned* __restrict__ vph, const unsigned* __restrict__ vpl,
    float* __restrict__ o)
{
    extern __shared__ unsigned sw_[];
    unsigned* Kph = sw_;
    unsigned* Kpl = Kph + 64 * KPP;
    unsigned* Vph = Kpl + 64 * KPP;
    unsigned* Vpl = Vph + 32 * VPP;

    const int tid = threadIdx.x;
    const int lane = tid & 31, wm = tid >> 5;
    const int l4 = lane >> 2, lk = lane & 3;
    const int iblk = (int)gridDim.x - 1 - (int)blockIdx.x;
    const int bh = blockIdx.y;
    const int b = bh >> 4, h = bh & 15;
    const size_t rowbase = (size_t)b * SEQ;
    const int m0 = iblk * 128;
    const float scale = 0.08838834764831845f;

    unsigned qh[8][4], ql[8][4];
    {
        const int r0 = m0 + wm * 16 + l4;
        #pragma unroll
        for (int s = 0; s < 8; s++) {
            #pragma unroll
            for (int f = 0; f < 4; f++) {
                int r = r0 + ((f & 1) ? 8 : 0);
                int d = 16 * s + 2 * lk + ((f & 2) ? 8 : 0);
                float2 qv = *(const float2*)(q + (rowbase + r) * EMB + h * DHEAD + d);
                float x = qv.x * scale, y = qv.y * scale;
                __nv_bfloat16 hx, lx, hy, ly;
                split_bf(x, hx, lx); split_bf(y, hy, ly);
                qh[s][f] = pack_bf2(hx, hy);
                ql[s][f] = pack_bf2(lx, ly);
            }
        }
    }

    float mr0 = -1e30f, mr1 = -1e30f, lr0 = 0.f, lr1 = 0.f;
    float oacc[16][4];
    #pragma unroll
    for (int nt = 0; nt < 16; nt++)
        #pragma unroll
        for (int i = 0; i < 4; i++) oacc[nt][i] = 0.f;

    const size_t kbase = (size_t)bh * SEQ * 64;
    const size_t vbase = (size_t)bh * 1024 * 128;

    const int ntiles = 2 * iblk + 2;
    for (int j = 0; j < ntiles; j++) {
        #pragma unroll
        for (int i = 0; i < 4; i++) {
            int lin = tid + 256 * i;            // 1024 uint4 slots
            int r = lin >> 4, c4 = (lin & 15) << 2;
            size_t src = kbase + (size_t)(j * 64 + r) * 64 + c4;
            *(uint4*)&Kph[r * KPP + c4] = *(const uint4*)(kph + src);
            *(uint4*)&Kpl[r * KPP + c4] = *(const uint4*)(kpl + src);
        }
        #pragma unroll
        for (int i = 0; i < 4; i++) {
            int lin = tid + 256 * i;
            int r = lin >> 5, c4 = (lin & 31) << 2;
            size_t src = vbase + (size_t)(j * 32 + r) * 128 + c4;
            *(uint4*)&Vph[r * VPP + c4] = *(const uint4*)(vph + src);
            *(uint4*)&Vpl[r * VPP + c4] = *(const uint4*)(vpl + src);
        }
        __syncthreads();

        float sacc[8][4];
        #pragma unroll
        for (int nt = 0; nt < 8; nt++)
            #pragma unroll
            for (int i = 0; i < 4; i++) sacc[nt][i] = 0.f;

        #pragma unroll
        for (int s = 0; s < 8; s++) {
            #pragma unroll
            for (int nt = 0; nt < 8; nt++) {
                int kr = (nt * 8 + l4) * KPP + 8 * s + lk;
                unsigned b_hi[2], b_lo[2];
                b_hi[0] = Kph[kr];
                b_hi[1] = Kph[kr + 4];
                b_lo[0] = Kpl[kr];
                b_lo[1] = Kpl[kr + 4];
                mma_bf16(sacc[nt], qh[s], b_hi);
                mma_bf16(sacc[nt], qh[s], b_lo);
                mma_bf16(sacc[nt], ql[s], b_hi);
            }
        }

        if (j >= 2 * iblk) {
            int row0 = m0 + wm * 16 + l4;
            #pragma unroll
            for (int nt = 0; nt < 8; nt++) {
                int col = j * 64 + nt * 8 + 2 * lk;
                if (col     > row0)     sacc[nt][0] = -1e30f;
                if (col + 1 > row0)     sacc[nt][1] = -1e30f;
                if (col     > row0 + 8) sacc[nt][2] = -1e30f;
                if (col + 1 > row0 + 8) sacc[nt][3] = -1e30f;
            }
        }

        float mx0 = -1e30f, mx1 = -1e30f;
        #pragma unroll
        for (int nt = 0; nt < 8; nt++) {
            mx0 = fmaxf(mx0, fmaxf(sacc[nt][0], sacc[nt][1]));
            mx1 = fmaxf(mx1, fmaxf(sacc[nt][2], sacc[nt][3]));
        }
        mx0 = fmaxf(mx0, __shfl_xor_sync(0xffffffffu, mx0, 1));
        mx0 = fmaxf(mx0, __shfl_xor_sync(0xffffffffu, mx0, 2));
        mx1 = fmaxf(mx1, __shfl_xor_sync(0xffffffffu, mx1, 1));
        mx1 = fmaxf(mx1, __shfl_xor_sync(0xffffffffu, mx1, 2));

        float mn0 = fmaxf(mr0, mx0), mn1 = fmaxf(mr1, mx1);
        float al0 = __expf(mr0 - mn0), al1 = __expf(mr1 - mn1);
        mr0 = mn0; mr1 = mn1;

        unsigned ph01[8], ph23[8];
        float rs0 = 0.f, rs1 = 0.f;
        #pragma unroll
        for (int nt = 0; nt < 8; nt++) {
            float p0 = __expf(sacc[nt][0] - mn0);
            float p1 = __expf(sacc[nt][1] - mn0);
            float p2 = __expf(sacc[nt][2] - mn1);
            float p3 = __expf(sacc[nt][3] - mn1);
            rs0 += p0 + p1; rs1 += p2 + p3;
            ph01[nt] = pack_h2(__float2half_rn(p0), __float2half_rn(p1));
            ph23[nt] = pack_h2(__float2half_rn(p2), __float2half_rn(p3));
        }
        rs0 += __shfl_xor_sync(0xffffffffu, rs0, 1);
        rs0 += __shfl_xor_sync(0xffffffffu, rs0, 2);
        rs1 += __shfl_xor_sync(0xffffffffu, rs1, 1);
        rs1 += __shfl_xor_sync(0xffffffffu, rs1, 2);
        lr0 = lr0 * al0 + rs0;
        lr1 = lr1 * al1 + rs1;

        #pragma unroll
        for (int nt = 0; nt < 16; nt++) {
            oacc[nt][0] *= al0; oacc[nt][1] *= al0;
            oacc[nt][2] *= al1; oacc[nt][3] *= al1;
        }

        #pragma unroll
        for (int t = 0; t < 4; t++) {
            unsigned pa[4];
            pa[0] = ph01[2 * t];
            pa[1] = ph23[2 * t];
            pa[2] = ph01[2 * t + 1];
            pa[3] = ph23[2 * t + 1];
            #pragma unroll
            for (int nt = 0; nt < 16; nt++) {
                int vr = (8 * t + lk) * VPP + nt * 8 + l4;
                unsigned b_hi[2], b_lo[2];
                b_hi[0] = Vph[vr];
                b_hi[1] = Vph[vr + 4 * VPP];
                b_lo[0] = Vpl[vr];
                b_lo[1] = Vpl[vr + 4 * VPP];
                mma_f16_f32(oacc[nt], pa, b_hi);
                mma_f16_f32(oacc[nt], pa, b_lo);
            }
        }
        __syncthreads();
    }

    float il0 = 1.f / lr0, il1 = 1.f / lr1;
    int row0 = m0 + wm * 16 + l4;
    #pragma unroll
    for (int nt = 0; nt < 16; nt++) {
        int col = h * DHEAD + nt * 8 + 2 * lk;
        float2 o0 = make_float2(oacc[nt][0] * il0, oacc[nt][1] * il0);
        float2 o1 = make_float2(oacc[nt][2] * il1, oacc[nt][3] * il1);
        *(float2*)(o + (rowbase + row0) * EMB + col)     = o0;
        *(float2*)(o + (rowbase + row0 + 8) * EMB + col) = o1;
    }
}

// ---------------------------------------------------------------------------
extern "C" void kernel_launch(void* const* d_in, const int* in_sizes, int n_in,
                              void* d_out, int out_size)
{
    const float* x    = (const float*)d_in[0];
    const float* mask = (const float*)d_in[1];
    const float* Wq = (const float*)d_in[2];  const float* bq = (const float*)d_in[3];
    const float* Aq = (const float*)d_in[4];  const float* Bq = (const float*)d_in[5];
    const float* Cq = (const float*)d_in[6];  const float* Rq = (const float*)d_in[7];
    const float* Wk = (const float*)d_in[8];  const float* bk = (const float*)d_in[9];
    const float* Ak = (const float*)d_in[10]; const float* Bk = (const float*)d_in[11];
    const float* Ck = (const float*)d_in[12]; const float* Rk = (const float*)d_in[13];
    const float* Wv = (const float*)d_in[14]; const float* bv = (const float*)d_in[15];
    const float* Av = (const float*)d_in[16]; const float* Bv = (const float*)d_in[17];
    const float* Cv = (const float*)d_in[18]; const float* Rv = (const float*)d_in[19];
    const float* Wo = (const float*)d_in[20]; const float* Ao = (const float*)d_in[21];
    const float* Bo = (const float*)d_in[22]; const float* Co = (const float*)d_in[23];
    const float* Ro = (const float*)d_in[24];

    float *q, *k, *v, *att, *hx;
    unsigned *kph, *kpl, *vph, *vpl;
    cudaGetSymbolAddress((void**)&q,   g_q);
    cudaGetSymbolAddress((void**)&k,   g_k);
    cudaGetSymbolAddress((void**)&v,   g_v);
    cudaGetSymbolAddress((void**)&att, g_att);
    cudaGetSymbolAddress((void**)&hx,  g_haux);
    cudaGetSymbolAddress((void**)&kph, g_kph);
    cudaGetSymbolAddress((void**)&kpl, g_kpl);
    cudaGetSymbolAddress((void**)&vph, g_vph);
    cudaGetSymbolAddress((void**)&vpl, g_vpl);

    float* hq = hx;
    float* hk = hx + (size_t)ROWS * 96;
    float* hv = hx + (size_t)ROWS * 96 * 2;
    float* ho = hx + (size_t)ROWS * 96 * 3;

    cudaFuncSetAttribute(flash_mma,
                         cudaFuncAttributeMaxDynamicSharedMemorySize, FA2_SMEM);

    dim3 ggrid(EMB / 64, ROWS / 128);   // (32, 32)

    // aux terms for q/k/v
    aux_gemm<<<dim3(3, ROWS / 128), 256>>>(x, mask, Aq, Cq, Ak, Ck, Av, Cv, hq, hk, hv);
    // projections (fp16-split tensor cores)
    gemm_f16<<<ggrid, 256>>>(x, hq, Wq, Bq, Rq, bq, q);
    gemm_f16<<<ggrid, 256>>>(x, hk, Wk, Bk, Rk, bk, k);
    gemm_f16<<<ggrid, 256>>>(x, hv, Wv, Bv, Rv, bv, v);
    // rope q in-place, rope+pack k; pack v (fp16 hi/lo)
    rope_pack<<<(ROWS * NHEAD * 32 + 255) / 256, 256>>>(q, k, kph, kpl);
    vpack<<<(32 * 1024 * 128 + 255) / 256, 256>>>(v, vph, vpl);
    // flash attention
    flash_mma<<<dim3(SEQ / 128, BATCH * NHEAD), 256, FA2_SMEM>>>(q, kph, kpl, vph, vpl, att);
    // output projection
    aux_gemm<<<dim3(1, ROWS / 128), 256>>>(att, mask, Ao, Co, Ao, Co, Ao, Co, ho, ho, ho);
    gemm_f16<<<ggrid, 256>>>(att, ho, Wo, Bo, Ro, nullptr, (float*)d_out);
}

// round 11
// speedup vs baseline: 1.9787x; 1.1748x over previous
#include <cuda_runtime.h>
#include <cuda_bf16.h>
#include <cuda_fp16.h>
#include <cstdint>
#include <math.h>

#define BATCH 2
#define SEQ   2048
#define EMB   2048
#define NHEAD 16
#define DHEAD 128
#define NEXP_ 64
#define RLORA 32
#define ROWS  4096
#define KAUG  2144

// ---------------- scratch ----------------
__device__ float g_q[(size_t)ROWS * EMB];
__device__ float g_k[(size_t)ROWS * EMB];
__device__ float g_v[(size_t)ROWS * EMB];
__device__ float g_att[(size_t)ROWS * EMB];
__device__ float g_haux[4][(size_t)ROWS * 96];
// packed tiles for flash: K bf16 hi/lo along d-pairs, V fp16 hi/lo along k-pairs
__device__ unsigned g_kph[(size_t)32 * 2048 * 64];
__device__ unsigned g_kpl[(size_t)32 * 2048 * 64];
__device__ unsigned g_vph[(size_t)32 * 1024 * 128];
__device__ unsigned g_vpl[(size_t)32 * 1024 * 128];

// ---------------- helpers ----------------
__device__ __forceinline__ unsigned pack_bf2(__nv_bfloat16 a, __nv_bfloat16 b) {
    return (unsigned)__bfloat16_as_ushort(a) | ((unsigned)__bfloat16_as_ushort(b) << 16);
}
__device__ __forceinline__ void split_bf(float x, __nv_bfloat16& hi, __nv_bfloat16& lo) {
    hi = __float2bfloat16_rn(x);
    lo = __float2bfloat16_rn(x - __bfloat162float(hi));
}
__device__ __forceinline__ unsigned pack_h2(__half a, __half b) {
    __half2 t = __halves2half2(a, b);
    return *(unsigned*)&t;
}
__device__ __forceinline__ void split_h_plain(float x, __half& hi, __half& lo) {
    hi = __float2half_rn(x);
    lo = __float2half_rn(x - __half2float(hi));
}
__device__ __forceinline__ void mma_bf16(float* c, const unsigned* a, const unsigned* b) {
    asm volatile(
        "mma.sync.aligned.m16n8k16.row.col.f32.bf16.bf16.f32 "
        "{%0,%1,%2,%3}, {%4,%5,%6,%7}, {%8,%9}, {%0,%1,%2,%3};"
        : "+f"(c[0]), "+f"(c[1]), "+f"(c[2]), "+f"(c[3])
        : "r"(a[0]), "r"(a[1]), "r"(a[2]), "r"(a[3]), "r"(b[0]), "r"(b[1]));
}
__device__ __forceinline__ void mma_f16_f32(float* c, const unsigned* a, const unsigned* b) {
    asm volatile(
        "mma.sync.aligned.m16n8k16.row.col.f32.f16.f16.f32 "
        "{%0,%1,%2,%3}, {%4,%5,%6,%7}, {%8,%9}, {%0,%1,%2,%3};"
        : "+f"(c[0]), "+f"(c[1]), "+f"(c[2]), "+f"(c[3])
        : "r"(a[0]), "r"(a[1]), "r"(a[2]), "r"(a[3]), "r"(b[0]), "r"(b[1]));
}

#define L2E 1.4426950408889634f

// fast exp2 on the FMA pipe: t in log2 domain, t <= ~0 expected.
// magic-add rounding + degree-5 poly on [-0.5,0.5] + exponent insert.
__device__ __forceinline__ float exp2q(float t) {
    t = fmaxf(t, -126.f);
    float z = t + 12582912.f;               // 1.5*2^23
    int ni = __float_as_int(z) - 0x4B400000;
    float r = t - (z - 12582912.f);         // [-0.5, 0.5]
    float p = 1.3333558146e-3f;
    p = fmaf(p, r, 9.6181291876e-3f);
    p = fmaf(p, r, 5.5504108665e-2f);
    p = fmaf(p, r, 2.4022650696e-1f);
    p = fmaf(p, r, 6.9314718056e-1f);
    p = fmaf(p, r, 1.0f);
    return p * __int_as_float((ni + 127) << 23);
}

// ---------------------------------------------------------------------------
// aux GEMM on tensor cores (bf16 split): h[0:32]=silu(x@A^T),
// h[32:96]=silu(x@C^T)*mask. Tile 128x96x32, 8 warps (4m x 2n), warp 32x48.
// ---------------------------------------------------------------------------
__global__ __launch_bounds__(256) void aux_mma(
    const float* __restrict__ act, const float* __restrict__ mask,
    const float* __restrict__ A0, const float* __restrict__ C0,
    const float* __restrict__ A1, const float* __restrict__ C1,
    const float* __restrict__ A2, const float* __restrict__ C2,
    float* __restrict__ h0, float* __restrict__ h1, float* __restrict__ h2)
{
    __shared__ unsigned Ah[128][20], Al[128][20];
    __shared__ unsigned Bh[96][20],  Blo[96][20];

    const int proj = blockIdx.x;
    const int m0 = blockIdx.y * 128;
    const float* A = (proj == 0) ? A0 : ((proj == 1) ? A1 : A2);
    const float* C = (proj == 0) ? C0 : ((proj == 1) ? C1 : C2);
    float* hout    = (proj == 0) ? h0 : ((proj == 1) ? h1 : h2);

    const int tid = threadIdx.x;
    const int lane = tid & 31, wid = tid >> 5;
    const int l4 = lane >> 2, lk = lane & 3;
    const int warp_m = wid & 3, warp_n = wid >> 2;

    float c[2][6][4];
    #pragma unroll
    for (int mt = 0; mt < 2; mt++)
        #pragma unroll
        for (int nt = 0; nt < 6; nt++)
            #pragma unroll
            for (int i = 0; i < 4; i++) c[mt][nt][i] = 0.f;

    for (int k0 = 0; k0 < EMB; k0 += 32) {
        #pragma unroll
        for (int i = 0; i < 4; i++) {
            int lin = tid + 256 * i;
            int r = lin >> 3, c4 = (lin & 7) << 2;
            float4 va = *(const float4*)(act + (size_t)(m0 + r) * EMB + k0 + c4);
            __nv_bfloat16 hx, lx, hy, ly, hz, lz, hw, lw;
            split_bf(va.x, hx, lx); split_bf(va.y, hy, ly);
            split_bf(va.z, hz, lz); split_bf(va.w, hw, lw);
            int wofs = c4 >> 1;
            *(uint2*)&Ah[r][wofs] = make_uint2(pack_bf2(hx, hy), pack_bf2(hz, hw));
            *(uint2*)&Al[r][wofs] = make_uint2(pack_bf2(lx, ly), pack_bf2(lz, lw));
        }
        #pragma unroll
        for (int i = 0; i < 3; i++) {
            int lin = tid + 256 * i;
            if (lin < 768) {
                int r = lin >> 3, c4 = (lin & 7) << 2;
                const float* src = (r < 32) ? (A + (size_t)r * EMB)
                                            : (C + (size_t)(r - 32) * EMB);
                float4 vb = *(const float4*)(src + k0 + c4);
                __nv_bfloat16 hx, lx, hy, ly, hz, lz, hw, lw;
                split_bf(vb.x, hx, lx); split_bf(vb.y, hy, ly);
                split_bf(vb.z, hz, lz); split_bf(vb.w, hw, lw);
                int wofs = c4 >> 1;
                *(uint2*)&Bh[r][wofs]  = make_uint2(pack_bf2(hx, hy), pack_bf2(hz, hw));
                *(uint2*)&Blo[r][wofs] = make_uint2(pack_bf2(lx, ly), pack_bf2(lz, lw));
            }
        }
        __syncthreads();

        #pragma unroll
        for (int ks = 0; ks < 2; ks++) {
            const int kw = ks * 8;
            unsigned ah[2][4], al[2][4];
            #pragma unroll
            for (int mt = 0; mt < 2; mt++) {
                int rb = warp_m * 32 + mt * 16 + l4;
                ah[mt][0] = Ah[rb][kw + lk];
                ah[mt][1] = Ah[rb + 8][kw + lk];
                ah[mt][2] = Ah[rb][kw + 4 + lk];
                ah[mt][3] = Ah[rb + 8][kw + 4 + lk];
                al[mt][0] = Al[rb][kw + lk];
                al[mt][1] = Al[rb + 8][kw + lk];
                al[mt][2] = Al[rb][kw + 4 + lk];
                al[mt][3] = Al[rb + 8][kw + 4 + lk];
            }
            #pragma unroll
            for (int nt = 0; nt < 6; nt++) {
                int cb = warp_n * 48 + nt * 8 + l4;
                unsigned bh[2], bl[2];
                bh[0] = Bh[cb][kw + lk];
                bh[1] = Bh[cb][kw + 4 + lk];
                bl[0] = Blo[cb][kw + lk];
                bl[1] = Blo[cb][kw + 4 + lk];
                #pragma unroll
                for (int mt = 0; mt < 2; mt++) {
                    mma_bf16(c[mt][nt], ah[mt], bh);
                    mma_bf16(c[mt][nt], ah[mt], bl);
                    mma_bf16(c[mt][nt], al[mt], bh);
                }
            }
        }
        __syncthreads();
    }

    // epilogue: silu (+ mask for expert cols), fp32 out stride 96
    #pragma unroll
    for (int mt = 0; mt < 2; mt++) {
        int r0 = m0 + warp_m * 32 + mt * 16 + l4;
        #pragma unroll
        for (int nt = 0; nt < 6; nt++) {
            int u = warp_n * 48 + nt * 8 + 2 * lk;
            #pragma unroll
            for (int half = 0; half < 2; half++) {
                int row = r0 + half * 8;
                float v0 = c[mt][nt][half * 2 + 0];
                float v1 = c[mt][nt][half * 2 + 1];
                float s0 = v0 / (1.f + __expf(-v0));
                float s1 = v1 / (1.f + __expf(-v1));
                if (u >= 32)     s0 *= mask[(size_t)row * NEXP_ + (u - 32)];
                if (u + 1 >= 32) s1 *= mask[(size_t)row * NEXP_ + (u + 1 - 32)];
                hout[(size_t)row * 96 + u]     = s0;
                hout[(size_t)row * 96 + u + 1] = s1;
            }
        }
    }
}

// ---------------------------------------------------------------------------
// K-augmented GEMM on tensor cores (split-bf16, 3x mma) — proven R5 version.
// Block 128x128x32, 8 warps (4m x 2n), warp tile 32x64.
// ---------------------------------------------------------------------------
#define GP 20

__global__ __launch_bounds__(256, 2) void gemm_mma(
    const float* __restrict__ act, const float* __restrict__ haux,
    const float* __restrict__ Wd,  const float* __restrict__ Bl,
    const float* __restrict__ Rr,  const float* __restrict__ bias,
    float* __restrict__ out)
{
    __shared__ unsigned As_hi[128][GP], As_lo[128][GP];
    __shared__ unsigned Bs_hi[128][GP], Bs_lo[128][GP];

    const int tid = threadIdx.x;
    const int lane = tid & 31, wid = tid >> 5;
    const int l4 = lane >> 2, lk = lane & 3;
    const int warp_m = wid & 3, warp_n = wid >> 2;
    const int m0 = blockIdx.y * 128, n0 = blockIdx.x * 128;

    float c[2][8][4];
    #pragma unroll
    for (int mt = 0; mt < 2; mt++)
        #pragma unroll
        for (int nt = 0; nt < 8; nt++)
            #pragma unroll
            for (int i = 0; i < 4; i++) c[mt][nt][i] = 0.f;

    for (int k0 = 0; k0 < KAUG; k0 += 32) {
        const float* asrc; int lda, kof;
        if (k0 < EMB) { asrc = act;  lda = EMB; kof = k0; }
        else          { asrc = haux; lda = 96;  kof = k0 - EMB; }

        const float* wsrc; int ldw, kofw;
        if (k0 < EMB)              { wsrc = Wd; ldw = EMB;   kofw = k0; }
        else if (k0 < EMB + RLORA) { wsrc = Bl; ldw = RLORA; kofw = k0 - EMB; }
        else                       { wsrc = Rr; ldw = NEXP_; kofw = k0 - EMB - RLORA; }

        #pragma unroll
        for (int i = 0; i < 4; i++) {
            int lin = tid + 256 * i;
            int r = lin >> 3, c4 = (lin & 7) << 2;
            float4 va = *(const float4*)(asrc + (size_t)(m0 + r) * lda + kof + c4);
            __nv_bfloat16 hx, lx, hy, ly, hz, lz, hw, lw;
            split_bf(va.x, hx, lx); split_bf(va.y, hy, ly);
            split_bf(va.z, hz, lz); split_bf(va.w, hw, lw);
            int wofs = c4 >> 1;
            *(uint2*)&As_hi[r][wofs] = make_uint2(pack_bf2(hx, hy), pack_bf2(hz, hw));
            *(uint2*)&As_lo[r][wofs] = make_uint2(pack_bf2(lx, ly), pack_bf2(lz, lw));
        }
        #pragma unroll
        for (int i = 0; i < 4; i++) {
            int lin = tid + 256 * i;
            int r = lin >> 3, c4 = (lin & 7) << 2;
            float4 vb = *(const float4*)(wsrc + (size_t)(n0 + r) * ldw + kofw + c4);
            __nv_bfloat16 hx, lx, hy, ly, hz, lz, hw, lw;
            split_bf(vb.x, hx, lx); split_bf(vb.y, hy, ly);
            split_bf(vb.z, hz, lz); split_bf(vb.w, hw, lw);
            int wofs = c4 >> 1;
            *(uint2*)&Bs_hi[r][wofs] = make_uint2(pack_bf2(hx, hy), pack_bf2(hz, hw));
            *(uint2*)&Bs_lo[r][wofs] = make_uint2(pack_bf2(lx, ly), pack_bf2(lz, lw));
        }
        __syncthreads();

        #pragma unroll
        for (int ks = 0; ks < 2; ks++) {
            const int kw = ks * 8;
            unsigned a_hi[2][4], a_lo[2][4];
            #pragma unroll
            for (int mt = 0; mt < 2; mt++) {
                int rb = warp_m * 32 + mt * 16 + l4;
                a_hi[mt][0] = As_hi[rb][kw + lk];
                a_hi[mt][1] = As_hi[rb + 8][kw + lk];
                a_hi[mt][2] = As_hi[rb][kw + 4 + lk];
                a_hi[mt][3] = As_hi[rb + 8][kw + 4 + lk];
                a_lo[mt][0] = As_lo[rb][kw + lk];
                a_lo[mt][1] = As_lo[rb + 8][kw + lk];
                a_lo[mt][2] = As_lo[rb][kw + 4 + lk];
                a_lo[mt][3] = As_lo[rb + 8][kw + 4 + lk];
            }
            #pragma unroll
            for (int nt = 0; nt < 8; nt++) {
                int cb = warp_n * 64 + nt * 8 + l4;
                unsigned b_hi[2], b_lo[2];
                b_hi[0] = Bs_hi[cb][kw + lk];
                b_hi[1] = Bs_hi[cb][kw + 4 + lk];
                b_lo[0] = Bs_lo[cb][kw + lk];
                b_lo[1] = Bs_lo[cb][kw + 4 + lk];
                #pragma unroll
                for (int mt = 0; mt < 2; mt++) {
                    mma_bf16(c[mt][nt], a_hi[mt], b_hi);
                    mma_bf16(c[mt][nt], a_hi[mt], b_lo);
                    mma_bf16(c[mt][nt], a_lo[mt], b_hi);
                }
            }
        }
        __syncthreads();
    }

    float2 bv[8];
    #pragma unroll
    for (int nt = 0; nt < 8; nt++) {
        int col = n0 + warp_n * 64 + nt * 8 + 2 * lk;
        if (bias) bv[nt] = *(const float2*)(bias + col);
        else      bv[nt] = make_float2(0.f, 0.f);
    }
    #pragma unroll
    for (int mt = 0; mt < 2; mt++) {
        int r0 = m0 + warp_m * 32 + mt * 16 + l4;
        #pragma unroll
        for (int nt = 0; nt < 8; nt++) {
            int col = n0 + warp_n * 64 + nt * 8 + 2 * lk;
            float2 o0 = make_float2(c[mt][nt][0] + bv[nt].x, c[mt][nt][1] + bv[nt].y);
            float2 o1 = make_float2(c[mt][nt][2] + bv[nt].x, c[mt][nt][3] + bv[nt].y);
            *(float2*)(out + (size_t)r0 * EMB + col)       = o0;
            *(float2*)(out + (size_t)(r0 + 8) * EMB + col) = o1;
        }
    }
}

// ---------------------------------------------------------------------------
// rope_pack: rope q in-place (fp32); rope k -> packed bf16 hi/lo, K[bh][s][dw]
// ---------------------------------------------------------------------------
__global__ void rope_pack(float* __restrict__ q, const float* __restrict__ k,
                          unsigned* __restrict__ kph, unsigned* __restrict__ kpl)
{
    int idx = blockIdx.x * blockDim.x + threadIdx.x;   // ROWS*16*32
    if (idx >= ROWS * NHEAD * 32) return;
    int jj  = idx & 31;
    int h   = (idx >> 5) & 15;
    int row = idx >> 9;
    int s   = row & (SEQ - 1);
    int b   = row >> 11;

    float sn[2], cs[2];
    #pragma unroll
    for (int t = 0; t < 2; t++) {
        int d = 2 * jj + t;
        float e = (float)(2 * d) * (1.0f / 128.0f);
        float inv = powf(10000.0f, -e);
        sincosf((float)s * inv, &sn[t], &cs[t]);
    }

    size_t base = (size_t)row * EMB + h * DHEAD;
    float qlo[2], qhi2[2], klo[2], khi2[2];
    #pragma unroll
    for (int t = 0; t < 2; t++) {
        int d = 2 * jj + t;
        float x1 = q[base + d], x2 = q[base + d + 64];
        qlo[t]  = x1 * cs[t] - x2 * sn[t];
        qhi2[t] = x2 * cs[t] + x1 * sn[t];
        float y1 = k[base + d], y2 = k[base + d + 64];
        klo[t]  = y1 * cs[t] - y2 * sn[t];
        khi2[t] = y2 * cs[t] + y1 * sn[t];
    }
    #pragma unroll
    for (int t = 0; t < 2; t++) {
        q[base + 2 * jj + t]      = qlo[t];
        q[base + 2 * jj + t + 64] = qhi2[t];
    }
    int bh = b * NHEAD + h;
    size_t kbase = ((size_t)bh * SEQ + s) * 64;
    __nv_bfloat16 h0, l0, h1, l1;
    split_bf(klo[0], h0, l0); split_bf(klo[1], h1, l1);
    kph[kbase + jj] = pack_bf2(h0, h1);
    kpl[kbase + jj] = pack_bf2(l0, l1);
    split_bf(khi2[0], h0, l0); split_bf(khi2[1], h1, l1);
    kph[kbase + jj + 32] = pack_bf2(h0, h1);
    kpl[kbase + jj + 32] = pack_bf2(l0, l1);
}

// ---------------------------------------------------------------------------
// vpack: V[bh][kw][nn] = pack_f16(V[s=2kw][nn], V[2kw+1][nn]) fp16 hi/lo
// ---------------------------------------------------------------------------
__global__ void vpack(const float* __restrict__ v,
                      unsigned* __restrict__ vph, unsigned* __restrict__ vpl)
{
    int idx = blockIdx.x * blockDim.x + threadIdx.x;   // 32*1024*128
    if (idx >= 32 * 1024 * 128) return;
    int nn = idx & 127;
    int kw = (idx >> 7) & 1023;
    int bh = idx >> 17;
    int b = bh >> 4, h = bh & 15;
    size_t addr = ((size_t)(b * SEQ + 2 * kw)) * EMB + h * DHEAD + nn;
    float v0 = v[addr], v1 = v[addr + EMB];
    __half h0, l0, h1, l1;
    split_h_plain(v0, h0, l0); split_h_plain(v1, h1, l1);
    vph[idx] = pack_h2(h0, h1);
    vpl[idx] = pack_h2(l0, l1);
}

// ---------------------------------------------------------------------------
// Flash attention: QK 3-term bf16 (prepacked K), PV 2-term fp16,
// softmax exp via FMA-pipe exp2 polynomial (MUFU avoided).
// ---------------------------------------------------------------------------
#define KPP 68
#define VPP 136
#define FA2_SMEM ((64 * KPP * 2 + 32 * VPP * 2) * 4)

__global__ __launch_bounds__(256) void flash_mma(
    const float* __restrict__ q,
    const unsigned* __restrict__ kph, const unsigned* __restrict__ kpl,
    const unsigned* __restrict__ vph, const unsigned* __restrict__ vpl,
    float* __restrict__ o)
{
    extern __shared__ unsigned sw_[];
    unsigned* Kph = sw_;
    unsigned* Kpl = Kph + 64 * KPP;
    unsigned* Vph = Kpl + 64 * KPP;
    unsigned* Vpl = Vph + 32 * VPP;

    const int tid = threadIdx.x;
    const int lane = tid & 31, wm = tid >> 5;
    const int l4 = lane >> 2, lk = lane & 3;
    const int iblk = (int)gridDim.x - 1 - (int)blockIdx.x;
    const int bh = blockIdx.y;
    const int b = bh >> 4, h = bh & 15;
    const size_t rowbase = (size_t)b * SEQ;
    const int m0 = iblk * 128;
    const float scale = 0.08838834764831845f;

    unsigned qh[8][4], ql[8][4];
    {
        const int r0 = m0 + wm * 16 + l4;
        #pragma unroll
        for (int s = 0; s < 8; s++) {
            #pragma unroll
            for (int f = 0; f < 4; f++) {
                int r = r0 + ((f & 1) ? 8 : 0);
                int d = 16 * s + 2 * lk + ((f & 2) ? 8 : 0);
                float2 qv = *(const float2*)(q + (rowbase + r) * EMB + h * DHEAD + d);
                float x = qv.x * scale, y = qv.y * scale;
                __nv_bfloat16 hx, lx, hy, ly;
                split_bf(x, hx, lx); split_bf(y, hy, ly);
                qh[s][f] = pack_bf2(hx, hy);
                ql[s][f] = pack_bf2(lx, ly);
            }
        }
    }

    float mr0 = -1e30f, mr1 = -1e30f, lr0 = 0.f, lr1 = 0.f;
    float oacc[16][4];
    #pragma unroll
    for (int nt = 0; nt < 16; nt++)
        #pragma unroll
        for (int i = 0; i < 4; i++) oacc[nt][i] = 0.f;

    const size_t kbase = (size_t)bh * SEQ * 64;
    const size_t vbase = (size_t)bh * 1024 * 128;

    const int ntiles = 2 * iblk + 2;
    for (int j = 0; j < ntiles; j++) {
        #pragma unroll
        for (int i = 0; i < 4; i++) {
            int lin = tid + 256 * i;            // 1024 uint4 slots
            int r = lin >> 4, c4 = (lin & 15) << 2;
            size_t src = kbase + (size_t)(j * 64 + r) * 64 + c4;
            *(uint4*)&Kph[r * KPP + c4] = *(const uint4*)(kph + src);
            *(uint4*)&Kpl[r * KPP + c4] = *(const uint4*)(kpl + src);
        }
        #pragma unroll
        for (int i = 0; i < 4; i++) {
            int lin = tid + 256 * i;
            int r = lin >> 5, c4 = (lin & 31) << 2;
            size_t src = vbase + (size_t)(j * 32 + r) * 128 + c4;
            *(uint4*)&Vph[r * VPP + c4] = *(const uint4*)(vph + src);
            *(uint4*)&Vpl[r * VPP + c4] = *(const uint4*)(vpl + src);
        }
        __syncthreads();

        float sacc[8][4];
        #pragma unroll
        for (int nt = 0; nt < 8; nt++)
            #pragma unroll
            for (int i = 0; i < 4; i++) sacc[nt][i] = 0.f;

        #pragma unroll
        for (int s = 0; s < 8; s++) {
            #pragma unroll
            for (int nt = 0; nt < 8; nt++) {
                int kr = (nt * 8 + l4) * KPP + 8 * s + lk;
                unsigned b_hi[2], b_lo[2];
                b_hi[0] = Kph[kr];
                b_hi[1] = Kph[kr + 4];
                b_lo[0] = Kpl[kr];
                b_lo[1] = Kpl[kr + 4];
                mma_bf16(sacc[nt], qh[s], b_hi);
                mma_bf16(sacc[nt], qh[s], b_lo);
                mma_bf16(sacc[nt], ql[s], b_hi);
            }
        }

        if (j >= 2 * iblk) {
            int row0 = m0 + wm * 16 + l4;
            #pragma unroll
            for (int nt = 0; nt < 8; nt++) {
                int col = j * 64 + nt * 8 + 2 * lk;
                if (col     > row0)     sacc[nt][0] = -1e30f;
                if (col + 1 > row0)     sacc[nt][1] = -1e30f;
                if (col     > row0 + 8) sacc[nt][2] = -1e30f;
                if (col + 1 > row0 + 8) sacc[nt][3] = -1e30f;
            }
        }

        float mx0 = -1e30f, mx1 = -1e30f;
        #pragma unroll
        for (int nt = 0; nt < 8; nt++) {
            mx0 = fmaxf(mx0, fmaxf(sacc[nt][0], sacc[nt][1]));
            mx1 = fmaxf(mx1, fmaxf(sacc[nt][2], sacc[nt][3]));
        }
        mx0 = fmaxf(mx0, __shfl_xor_sync(0xffffffffu, mx0, 1));
        mx0 = fmaxf(mx0, __shfl_xor_sync(0xffffffffu, mx0, 2));
        mx1 = fmaxf(mx1, __shfl_xor_sync(0xffffffffu, mx1, 1));
        mx1 = fmaxf(mx1, __shfl_xor_sync(0xffffffffu, mx1, 2));

        float mn0 = fmaxf(mr0, mx0), mn1 = fmaxf(mr1, mx1);
        float al0 = exp2q((mr0 - mn0) * L2E);
        float al1 = exp2q((mr1 - mn1) * L2E);
        mr0 = mn0; mr1 = mn1;
        float mnl0 = mn0 * L2E, mnl1 = mn1 * L2E;

        unsigned ph01[8], ph23[8];
        float rs0 = 0.f, rs1 = 0.f;
        #pragma unroll
        for (int nt = 0; nt < 8; nt++) {
            float p0 = exp2q(fmaf(sacc[nt][0], L2E, -mnl0));
            float p1 = exp2q(fmaf(sacc[nt][1], L2E, -mnl0));
            float p2 = exp2q(fmaf(sacc[nt][2], L2E, -mnl1));
            float p3 = exp2q(fmaf(sacc[nt][3], L2E, -mnl1));
            rs0 += p0 + p1; rs1 += p2 + p3;
            ph01[nt] = pack_h2(__float2half_rn(p0), __float2half_rn(p1));
            ph23[nt] = pack_h2(__float2half_rn(p2), __float2half_rn(p3));
        }
        rs0 += __shfl_xor_sync(0xffffffffu, rs0, 1);
        rs0 += __shfl_xor_sync(0xffffffffu, rs0, 2);
        rs1 += __shfl_xor_sync(0xffffffffu, rs1, 1);
        rs1 += __shfl_xor_sync(0xffffffffu, rs1, 2);
        lr0 = lr0 * al0 + rs0;
        lr1 = lr1 * al1 + rs1;

        #pragma unroll
        for (int nt = 0; nt < 16; nt++) {
            oacc[nt][0] *= al0; oacc[nt][1] *= al0;
            oacc[nt][2] *= al1; oacc[nt][3] *= al1;
        }

        #pragma unroll
        for (int t = 0; t < 4; t++) {
            unsigned pa[4];
            pa[0] = ph01[2 * t];
            pa[1] = ph23[2 * t];
            pa[2] = ph01[2 * t + 1];
            pa[3] = ph23[2 * t + 1];
            #pragma unroll
            for (int nt = 0; nt < 16; nt++) {
                int vr = (8 * t + lk) * VPP + nt * 8 + l4;
                unsigned b_hi[2], b_lo[2];
                b_hi[0] = Vph[vr];
                b_hi[1] = Vph[vr + 4 * VPP];
                b_lo[0] = Vpl[vr];
                b_lo[1] = Vpl[vr + 4 * VPP];
                mma_f16_f32(oacc[nt], pa, b_hi);
                mma_f16_f32(oacc[nt], pa, b_lo);
            }
        }
        __syncthreads();
    }

    float il0 = 1.f / lr0, il1 = 1.f / lr1;
    int row0 = m0 + wm * 16 + l4;
    #pragma unroll
    for (int nt = 0; nt < 16; nt++) {
        int col = h * DHEAD + nt * 8 + 2 * lk;
        float2 o0 = make_float2(oacc[nt][0] * il0, oacc[nt][1] * il0);
        float2 o1 = make_float2(oacc[nt][2] * il1, oacc[nt][3] * il1);
        *(float2*)(o + (rowbase + row0) * EMB + col)     = o0;
        *(float2*)(o + (rowbase + row0 + 8) * EMB + col) = o1;
    }
}

// ---------------------------------------------------------------------------
extern "C" void kernel_launch(void* const* d_in, const int* in_sizes, int n_in,
                              void* d_out, int out_size)
{
    const float* x    = (const float*)d_in[0];
    const float* mask = (const float*)d_in[1];
    const float* Wq = (const float*)d_in[2];  const float* bq = (const float*)d_in[3];
    const float* Aq = (const float*)d_in[4];  const float* Bq = (const float*)d_in[5];
    const float* Cq = (const float*)d_in[6];  const float* Rq = (const float*)d_in[7];
    const float* Wk = (const float*)d_in[8];  const float* bk = (const float*)d_in[9];
    const float* Ak = (const float*)d_in[10]; const float* Bk = (const float*)d_in[11];
    const float* Ck = (const float*)d_in[12]; const float* Rk = (const float*)d_in[13];
    const float* Wv = (const float*)d_in[14]; const float* bv = (const float*)d_in[15];
    const float* Av = (const float*)d_in[16]; const float* Bv = (const float*)d_in[17];
    const float* Cv = (const float*)d_in[18]; const float* Rv = (const float*)d_in[19];
    const float* Wo = (const float*)d_in[20]; const float* Ao = (const float*)d_in[21];
    const float* Bo = (const float*)d_in[22]; const float* Co = (const float*)d_in[23];
    const float* Ro = (const float*)d_in[24];

    float *q, *k, *v, *att, *hx;
    unsigned *kph, *kpl, *vph, *vpl;
    cudaGetSymbolAddress((void**)&q,   g_q);
    cudaGetSymbolAddress((void**)&k,   g_k);
    cudaGetSymbolAddress((void**)&v,   g_v);
    cudaGetSymbolAddress((void**)&att, g_att);
    cudaGetSymbolAddress((void**)&hx,  g_haux);
    cudaGetSymbolAddress((void**)&kph, g_kph);
    cudaGetSymbolAddress((void**)&kpl, g_kpl);
    cudaGetSymbolAddress((void**)&vph, g_vph);
    cudaGetSymbolAddress((void**)&vpl, g_vpl);

    float* hq = hx;
    float* hk = hx + (size_t)ROWS * 96;
    float* hv = hx + (size_t)ROWS * 96 * 2;
    float* ho = hx + (size_t)ROWS * 96 * 3;

    cudaFuncSetAttribute(flash_mma,
                         cudaFuncAttributeMaxDynamicSharedMemorySize, FA2_SMEM);

    dim3 ggrid(EMB / 128, ROWS / 128);   // (16, 32)

    // aux terms for q/k/v (tensor cores)
    aux_mma<<<dim3(3, ROWS / 128), 256>>>(x, mask, Aq, Cq, Ak, Ck, Av, Cv, hq, hk, hv);
    // projections (split-bf16 tensor cores, proven R5 kernel)
    gemm_mma<<<ggrid, 256>>>(x, hq, Wq, Bq, Rq, bq, q);
    gemm_mma<<<ggrid, 256>>>(x, hk, Wk, Bk, Rk, bk, k);
    gemm_mma<<<ggrid, 256>>>(x, hv, Wv, Bv, Rv, bv, v);
    // rope q in-place, rope+pack k; pack v (fp16 hi/lo)
    rope_pack<<<(ROWS * NHEAD * 32 + 255) / 256, 256>>>(q, k, kph, kpl);
    vpack<<<(32 * 1024 * 128 + 255) / 256, 256>>>(v, vph, vpl);
    // flash attention (poly exp on FMA pipe)
    flash_mma<<<dim3(SEQ / 128, BATCH * NHEAD), 256, FA2_SMEM>>>(q, kph, kpl, vph, vpl, att);
    // output projection
    aux_mma<<<dim3(1, ROWS / 128), 256>>>(att, mask, Ao, Co, Ao, Co, Ao, Co, ho, ho, ho);
    gemm_mma<<<ggrid, 256>>>(att, ho, Wo, Bo, Ro, nullptr, (float*)d_out);
}